// round 12
// baseline (speedup 1.0000x reference)
#include <cuda_runtime.h>
#include <cstdint>

// ---- int32/int64 robustness: harness may deliver int64 refs as int32.
__device__ __forceinline__ bool buf_is_i64(const void* p) {
    const int* q = (const int*)p;
    return (q[1] == 0) && (q[3] == 0) && (q[5] == 0);
}
__device__ __forceinline__ long long load_i(const void* p, int i, bool is64) {
    return is64 ? ((const long long*)p)[i] : (long long)((const int*)p)[i];
}

#define TPB   256
#define NWARP (TPB / 32)
#define MAXG  64          // max rows per group we support in smem

// One block per (n, group). Phase A: stream group's rows, reduce sum/sumsq.
// Phase B: immediately re-read the same rows (hot in L2) and normalize+store.
__global__ void __launch_bounds__(TPB) vgn_group_kernel(
    const float* __restrict__ x,
    float* __restrict__ out,
    const void* __restrict__ indexes,
    const float* __restrict__ weight,
    const float* __restrict__ bias,
    const void* __restrict__ group_sizes,
    int C, int G, int HW4, int NG)
{
    __shared__ int   s_idx[MAXG];
    __shared__ int   s_meta[2];              // cstart, glen
    __shared__ float s_w1[NWARP], s_w2[NWARP];
    __shared__ float s_mu, s_ivar;

    const int tid  = threadIdx.x;
    const int wid  = tid >> 5;
    const int lane = tid & 31;
    const int nfull = HW4 & ~255;

    for (int gi = blockIdx.x; gi < NG; gi += gridDim.x) {
        const int n = gi / G;
        const int g = gi - n * G;

        if (tid == 0) {
            const bool gs64 = buf_is_i64(group_sizes);
            int acc = 0;
            for (int k = 0; k < g; ++k) acc += (int)load_i(group_sizes, k, gs64);
            s_meta[0] = acc;
            s_meta[1] = (int)load_i(group_sizes, g, gs64);
        }
        __syncthreads();
        const int cstart = s_meta[0];
        const int glen   = s_meta[1];

        if (tid < glen) {
            const bool ix64 = buf_is_i64(indexes);
            s_idx[tid] = (int)load_i(indexes, n * C + cstart + tid, ix64);
        }
        __syncthreads();

        // ---------------- Phase A: stats over the group's rows ----------------
        float s1a = 0.f, s2a = 0.f, s1b = 0.f, s2b = 0.f;
        for (int j = wid; j < glen; j += NWARP) {
            const float4* __restrict__ p =
                (const float4*)(x + (size_t)s_idx[j] * (size_t)(HW4 * 4));
            for (int j0 = 0; j0 < nfull; j0 += 256) {
                float4 v[8];
                #pragma unroll
                for (int k = 0; k < 8; ++k) v[k] = p[j0 + (k << 5) + lane];
                #pragma unroll
                for (int k = 0; k < 8; k += 2) {
                    s1a += (v[k].x + v[k].y) + (v[k].z + v[k].w);
                    s2a += v[k].x*v[k].x + v[k].y*v[k].y + v[k].z*v[k].z + v[k].w*v[k].w;
                    s1b += (v[k+1].x + v[k+1].y) + (v[k+1].z + v[k+1].w);
                    s2b += v[k+1].x*v[k+1].x + v[k+1].y*v[k+1].y
                         + v[k+1].z*v[k+1].z + v[k+1].w*v[k+1].w;
                }
            }
            for (int jj = nfull + lane; jj < HW4; jj += 32) {
                float4 v = p[jj];
                s1a += (v.x + v.y) + (v.z + v.w);
                s2a += v.x*v.x + v.y*v.y + v.z*v.z + v.w*v.w;
            }
        }
        float s1 = s1a + s1b, s2 = s2a + s2b;
        #pragma unroll
        for (int o = 16; o; o >>= 1) {
            s1 += __shfl_down_sync(0xffffffffu, s1, o);
            s2 += __shfl_down_sync(0xffffffffu, s2, o);
        }
        if (lane == 0) { s_w1[wid] = s1; s_w2[wid] = s2; }
        __syncthreads();
        if (tid == 0) {
            float t1 = 0.f, t2 = 0.f;
            #pragma unroll
            for (int k = 0; k < NWARP; ++k) { t1 += s_w1[k]; t2 += s_w2[k]; }
            const float cnt  = (float)glen * (float)(HW4 * 4);
            const float mu   = t1 / cnt;
            const float var  = (t2 - cnt * mu * mu) / (cnt - 1.0f);
            s_mu = mu;
            s_ivar = rsqrtf(var + 1e-12f);
        }
        __syncthreads();
        const float mu = s_mu, ivar = s_ivar;

        // ---------------- Phase B: normalize (rows hot in L2) ------------------
        for (int j = wid; j < glen; j += NWARP) {
            const int c = cstart + j;
            const float a   = ivar * weight[c];
            const float bsh = bias[c] - mu * a;
            const size_t off = (size_t)s_idx[j] * (size_t)(HW4 * 4);
            const float4* __restrict__ px = (const float4*)(x + off);
            float4*       __restrict__ po = (float4*)(out + off);
            for (int j0 = 0; j0 < nfull; j0 += 256) {
                float4 v[8];
                #pragma unroll
                for (int k = 0; k < 8; ++k) v[k] = __ldcs(&px[j0 + (k << 5) + lane]);
                #pragma unroll
                for (int k = 0; k < 8; ++k) {
                    v[k].x = fmaf(v[k].x, a, bsh);
                    v[k].y = fmaf(v[k].y, a, bsh);
                    v[k].z = fmaf(v[k].z, a, bsh);
                    v[k].w = fmaf(v[k].w, a, bsh);
                }
                #pragma unroll
                for (int k = 0; k < 8; ++k) __stcs(&po[j0 + (k << 5) + lane], v[k]);
            }
            for (int jj = nfull + lane; jj < HW4; jj += 32) {
                float4 v = __ldcs(&px[jj]);
                v.x = fmaf(v.x, a, bsh); v.y = fmaf(v.y, a, bsh);
                v.z = fmaf(v.z, a, bsh); v.w = fmaf(v.w, a, bsh);
                __stcs(&po[jj], v);
            }
        }
        __syncthreads();   // protect smem reuse across the group loop
    }
}

extern "C" void kernel_launch(void* const* d_in, const int* in_sizes, int n_in,
                              void* d_out, int out_size)
{
    const float* x       = (const float*)d_in[0];
    const float* weight  = (const float*)d_in[1];
    const float* bias    = (const float*)d_in[2];
    const void*  gsizes  = d_in[3];
    const void*  indexes = d_in[4];
    float* out = (float*)d_out;

    const int C   = in_sizes[1];
    const int G   = in_sizes[3];
    const int NC  = in_sizes[4];
    const int HW  = in_sizes[0] / NC;
    const int HW4 = HW / 4;
    const int N   = NC / C;
    const int NG  = N * G;

    vgn_group_kernel<<<NG, TPB>>>(x, out, indexes, weight, bias, gsizes,
                                  C, G, HW4, NG);
}

// round 14
// speedup vs baseline: 1.0032x; 1.0032x over previous
#include <cuda_runtime.h>
#include <cstdint>

// ---- int32/int64 robustness: harness may deliver int64 refs as int32.
__device__ __forceinline__ bool buf_is_i64(const void* p) {
    const int* q = (const int*)p;
    return (q[1] == 0) && (q[3] == 0) && (q[5] == 0);
}
__device__ __forceinline__ long long load_i(const void* p, int i, bool is64) {
    return is64 ? ((const long long*)p)[i] : (long long)((const int*)p)[i];
}

#define TPB   256
#define NWARP (TPB / 32)
#define MAXG  64          // max rows per group supported in smem index cache

// One block per (n, group). Phase A: stream group's rows, reduce sum/sumsq.
// Phase B: immediately re-read the same rows (hot in L2) and normalize+store.
__global__ void __launch_bounds__(TPB) vgn_fused_kernel(
    const float* __restrict__ x,
    float* __restrict__ out,
    const void* __restrict__ indexes,
    const float* __restrict__ weight,
    const float* __restrict__ bias,
    const void* __restrict__ group_sizes,
    int C, int G, int HW4, int NG)
{
    __shared__ int   s_idx[MAXG];
    __shared__ int   s_meta[2];              // cstart, glen
    __shared__ float s_w1[NWARP], s_w2[NWARP];
    __shared__ float s_mu, s_ivar;

    const int tid  = threadIdx.x;
    const int wid  = tid >> 5;
    const int lane = tid & 31;
    const int nfull = HW4 & ~255;

    const int gi = blockIdx.x;
    if (gi >= NG) return;
    const int n = gi / G;
    const int g = gi - n * G;

    if (tid == 0) {
        const bool gs64 = buf_is_i64(group_sizes);
        int acc = 0;
        for (int k = 0; k < g; ++k) acc += (int)load_i(group_sizes, k, gs64);
        s_meta[0] = acc;
        s_meta[1] = (int)load_i(group_sizes, g, gs64);
    }
    __syncthreads();
    const int cstart = s_meta[0];
    const int glen   = s_meta[1];

    if (tid < glen) {
        const bool ix64 = buf_is_i64(indexes);
        s_idx[tid] = (int)load_i(indexes, n * C + cstart + tid, ix64);
    }
    __syncthreads();

    // ---------------- Phase A: stats over the group's rows ----------------
    float s1a = 0.f, s2a = 0.f, s1b = 0.f, s2b = 0.f;
    for (int j = wid; j < glen; j += NWARP) {
        const float4* __restrict__ p =
            (const float4*)(x + (size_t)s_idx[j] * (size_t)(HW4 * 4));
        for (int j0 = 0; j0 < nfull; j0 += 256) {
            float4 v[8];
            #pragma unroll
            for (int k = 0; k < 8; ++k) v[k] = p[j0 + (k << 5) + lane];
            #pragma unroll
            for (int k = 0; k < 8; k += 2) {
                s1a += (v[k].x + v[k].y) + (v[k].z + v[k].w);
                s2a += v[k].x*v[k].x + v[k].y*v[k].y + v[k].z*v[k].z + v[k].w*v[k].w;
                s1b += (v[k+1].x + v[k+1].y) + (v[k+1].z + v[k+1].w);
                s2b += v[k+1].x*v[k+1].x + v[k+1].y*v[k+1].y
                     + v[k+1].z*v[k+1].z + v[k+1].w*v[k+1].w;
            }
        }
        for (int jj = nfull + lane; jj < HW4; jj += 32) {
            float4 v = p[jj];
            s1a += (v.x + v.y) + (v.z + v.w);
            s2a += v.x*v.x + v.y*v.y + v.z*v.z + v.w*v.w;
        }
    }
    float s1 = s1a + s1b, s2 = s2a + s2b;
    #pragma unroll
    for (int o = 16; o; o >>= 1) {
        s1 += __shfl_down_sync(0xffffffffu, s1, o);
        s2 += __shfl_down_sync(0xffffffffu, s2, o);
    }
    if (lane == 0) { s_w1[wid] = s1; s_w2[wid] = s2; }
    __syncthreads();
    if (tid == 0) {
        float t1 = 0.f, t2 = 0.f;
        #pragma unroll
        for (int k = 0; k < NWARP; ++k) { t1 += s_w1[k]; t2 += s_w2[k]; }
        const float cnt  = (float)glen * (float)(HW4 * 4);
        const float mu   = t1 / cnt;
        const float var  = (t2 - cnt * mu * mu) / (cnt - 1.0f);
        s_mu = mu;
        s_ivar = rsqrtf(var + 1e-12f);
    }
    __syncthreads();
    const float mu = s_mu, ivar = s_ivar;

    // ---------------- Phase B: normalize (rows hot in L2) ------------------
    for (int j = wid; j < glen; j += NWARP) {
        const int c = cstart + j;
        const float a   = ivar * weight[c];
        const float bsh = bias[c] - mu * a;
        const size_t off = (size_t)s_idx[j] * (size_t)(HW4 * 4);
        const float4* __restrict__ px = (const float4*)(x + off);
        float4*       __restrict__ po = (float4*)(out + off);
        for (int j0 = 0; j0 < nfull; j0 += 256) {
            float4 v[8];
            #pragma unroll
            for (int k = 0; k < 8; ++k) v[k] = __ldcs(&px[j0 + (k << 5) + lane]);
            #pragma unroll
            for (int k = 0; k < 8; ++k) {
                v[k].x = fmaf(v[k].x, a, bsh);
                v[k].y = fmaf(v[k].y, a, bsh);
                v[k].z = fmaf(v[k].z, a, bsh);
                v[k].w = fmaf(v[k].w, a, bsh);
            }
            #pragma unroll
            for (int k = 0; k < 8; ++k) __stcs(&po[j0 + (k << 5) + lane], v[k]);
        }
        for (int jj = nfull + lane; jj < HW4; jj += 32) {
            float4 v = __ldcs(&px[jj]);
            v.x = fmaf(v.x, a, bsh); v.y = fmaf(v.y, a, bsh);
            v.z = fmaf(v.z, a, bsh); v.w = fmaf(v.w, a, bsh);
            __stcs(&po[jj], v);
        }
    }
}

extern "C" void kernel_launch(void* const* d_in, const int* in_sizes, int n_in,
                              void* d_out, int out_size)
{
    const float* x       = (const float*)d_in[0];
    const float* weight  = (const float*)d_in[1];
    const float* bias    = (const float*)d_in[2];
    const void*  gsizes  = d_in[3];
    const void*  indexes = d_in[4];
    float* out = (float*)d_out;

    const int C   = in_sizes[1];
    const int G   = in_sizes[3];
    const int NC  = in_sizes[4];
    const int HW  = in_sizes[0] / NC;
    const int HW4 = HW / 4;
    const int N   = NC / C;
    const int NG  = N * G;

    vgn_fused_kernel<<<NG, TPB>>>(x, out, indexes, weight, bias, gsizes,
                                  C, G, HW4, NG);
}

// round 15
// speedup vs baseline: 1.0382x; 1.0349x over previous
#include <cuda_runtime.h>
#include <cstdint>

// ---- int32/int64 robustness: harness may deliver int64 refs as int32.
__device__ __forceinline__ bool buf_is_i64(const void* p) {
    const int* q = (const int*)p;
    return (q[1] == 0) && (q[3] == 0) && (q[5] == 0);
}
__device__ __forceinline__ long long load_i(const void* p, int i, bool is64) {
    return is64 ? ((const long long*)p)[i] : (long long)((const int*)p)[i];
}

#define TPB   512
#define NWARP (TPB / 32)
#define MAXG  64          // max rows per group supported in smem index cache

// One block per (n, group). Work unit = HALF-ROW, so 2*glen units per group:
// for glen in {8,16,24,32} the unit count {16,32,48,64} is a multiple of 16
// warps -> perfect intra-block balance. Phase A streams units for sum/sumsq;
// phase B re-reads the same bytes (short reuse distance -> L2 hits) and stores.
__global__ void __launch_bounds__(TPB, 3) vgn_fused_kernel(
    const float* __restrict__ x,
    float* __restrict__ out,
    const void* __restrict__ indexes,
    const float* __restrict__ weight,
    const float* __restrict__ bias,
    const void* __restrict__ group_sizes,
    int C, int G, int HW4, int NG)
{
    __shared__ int   s_idx[MAXG];
    __shared__ int   s_meta[2];              // cstart, glen
    __shared__ float s_w1[NWARP], s_w2[NWARP];
    __shared__ float s_mu, s_ivar;

    const int tid  = threadIdx.x;
    const int wid  = tid >> 5;
    const int lane = tid & 31;
    const int HALF = HW4 >> 1;

    const int gi = blockIdx.x;
    if (gi >= NG) return;
    const int n = gi / G;
    const int g = gi - n * G;

    if (tid == 0) {
        const bool gs64 = buf_is_i64(group_sizes);
        int acc = 0;
        for (int k = 0; k < g; ++k) acc += (int)load_i(group_sizes, k, gs64);
        s_meta[0] = acc;
        s_meta[1] = (int)load_i(group_sizes, g, gs64);
    }
    __syncthreads();
    const int cstart = s_meta[0];
    const int glen   = s_meta[1];
    const int nu     = glen << 1;            // half-row units

    if (tid < glen) {
        const bool ix64 = buf_is_i64(indexes);
        s_idx[tid] = (int)load_i(indexes, n * C + cstart + tid, ix64);
    }
    __syncthreads();

    // ---------------- Phase A: stats over half-row units -------------------
    float s1a = 0.f, s2a = 0.f, s1b = 0.f, s2b = 0.f;
    for (int u = wid; u < nu; u += NWARP) {
        const int j = u >> 1;
        const int h = u & 1;
        const int hbeg = h ? HALF : 0;
        const int hlen = h ? (HW4 - HALF) : HALF;
        const float4* __restrict__ p =
            (const float4*)(x + (size_t)s_idx[j] * (size_t)(HW4 * 4)) + hbeg;
        const int full = hlen & ~127;        // batches of 128 float4 (MLP=4)
        for (int j0 = 0; j0 < full; j0 += 128) {
            float4 v[4];
            #pragma unroll
            for (int k = 0; k < 4; ++k) v[k] = p[j0 + (k << 5) + lane];
            #pragma unroll
            for (int k = 0; k < 4; k += 2) {
                s1a += (v[k].x + v[k].y) + (v[k].z + v[k].w);
                s2a += v[k].x*v[k].x + v[k].y*v[k].y + v[k].z*v[k].z + v[k].w*v[k].w;
                s1b += (v[k+1].x + v[k+1].y) + (v[k+1].z + v[k+1].w);
                s2b += v[k+1].x*v[k+1].x + v[k+1].y*v[k+1].y
                     + v[k+1].z*v[k+1].z + v[k+1].w*v[k+1].w;
            }
        }
        for (int jj = full + lane; jj < hlen; jj += 32) {
            float4 v = p[jj];
            s1a += (v.x + v.y) + (v.z + v.w);
            s2a += v.x*v.x + v.y*v.y + v.z*v.z + v.w*v.w;
        }
    }
    float s1 = s1a + s1b, s2 = s2a + s2b;
    #pragma unroll
    for (int o = 16; o; o >>= 1) {
        s1 += __shfl_down_sync(0xffffffffu, s1, o);
        s2 += __shfl_down_sync(0xffffffffu, s2, o);
    }
    if (lane == 0) { s_w1[wid] = s1; s_w2[wid] = s2; }
    __syncthreads();
    if (tid == 0) {
        float t1 = 0.f, t2 = 0.f;
        #pragma unroll
        for (int k = 0; k < NWARP; ++k) { t1 += s_w1[k]; t2 += s_w2[k]; }
        const float cnt  = (float)glen * (float)(HW4 * 4);
        const float mu   = t1 / cnt;
        const float var  = (t2 - cnt * mu * mu) / (cnt - 1.0f);
        s_mu = mu;
        s_ivar = rsqrtf(var + 1e-12f);
    }
    __syncthreads();
    const float mu = s_mu, ivar = s_ivar;

    // ---------------- Phase B: normalize (bytes hot in L2) -----------------
    for (int u = wid; u < nu; u += NWARP) {
        const int j = u >> 1;
        const int h = u & 1;
        const int hbeg = h ? HALF : 0;
        const int hlen = h ? (HW4 - HALF) : HALF;
        const int c = cstart + j;
        const float a   = ivar * weight[c];
        const float bsh = bias[c] - mu * a;
        const size_t off = (size_t)s_idx[j] * (size_t)(HW4 * 4);
        const float4* __restrict__ px = (const float4*)(x + off) + hbeg;
        float4*       __restrict__ po = (float4*)(out + off) + hbeg;
        const int full = hlen & ~127;
        for (int j0 = 0; j0 < full; j0 += 128) {
            float4 v[4];
            #pragma unroll
            for (int k = 0; k < 4; ++k) v[k] = __ldcs(&px[j0 + (k << 5) + lane]);
            #pragma unroll
            for (int k = 0; k < 4; ++k) {
                v[k].x = fmaf(v[k].x, a, bsh);
                v[k].y = fmaf(v[k].y, a, bsh);
                v[k].z = fmaf(v[k].z, a, bsh);
                v[k].w = fmaf(v[k].w, a, bsh);
            }
            #pragma unroll
            for (int k = 0; k < 4; ++k) __stcs(&po[j0 + (k << 5) + lane], v[k]);
        }
        for (int jj = full + lane; jj < hlen; jj += 32) {
            float4 v = __ldcs(&px[jj]);
            v.x = fmaf(v.x, a, bsh); v.y = fmaf(v.y, a, bsh);
            v.z = fmaf(v.z, a, bsh); v.w = fmaf(v.w, a, bsh);
            __stcs(&po[jj], v);
        }
    }
}

extern "C" void kernel_launch(void* const* d_in, const int* in_sizes, int n_in,
                              void* d_out, int out_size)
{
    const float* x       = (const float*)d_in[0];
    const float* weight  = (const float*)d_in[1];
    const float* bias    = (const float*)d_in[2];
    const void*  gsizes  = d_in[3];
    const void*  indexes = d_in[4];
    float* out = (float*)d_out;

    const int C   = in_sizes[1];
    const int G   = in_sizes[3];
    const int NC  = in_sizes[4];
    const int HW  = in_sizes[0] / NC;
    const int HW4 = HW / 4;
    const int N   = NC / C;
    const int NG  = N * G;

    vgn_fused_kernel<<<NG, TPB>>>(x, out, indexes, weight, bias, gsizes,
                                  C, G, HW4, NG);
}